// round 12
// baseline (speedup 1.0000x reference)
#include <cuda_runtime.h>
#include <cuda_fp16.h>
#include <cstdint>

// ---------------------------------------------------------------------------
// GCNEncoder: 8-layer GCN, N=100000, E=1.6M, F=15->64(x7)->64
// Layers 1..7 FUSED: block aggregates 128 nodes (warp-per-node CSR gather,
// interleaved (src,norm) pairs) into an smem fp16 tile, then applies W via
// HMMA 128x64x64 tile GEMM in the same kernel (fp32 accum), bias+act.
// PING-PONG buffers between layers (round-11 bug: in-place read/write race).
// Layer 0: SIMT 15->64 transform + warp-per-node agg.
// edge_index is int32 on device (JAX default, x64 disabled).
// ---------------------------------------------------------------------------

#define MAXN 131072
#define MAXE 1700000

__device__ __half g_t[MAXN * 64];        // ping buffer
__device__ __half g_hh[MAXN * 64];       // pong buffer
__device__ __half g_wh[7 * 4096];        // fp16 weights: Wm[0..5], Wl
__device__ float  g_deg[MAXN];
__device__ float  g_dinv[MAXN];
__device__ float  g_selfnorm[MAXN];
__device__ int    g_cnt[MAXN];
__device__ int    g_cursor[MAXN];
__device__ int    g_rowoff[MAXN + 1];
__device__ int    g_blkagg[128];
__device__ int    g_blkincl[128];
__device__ int    g_flag[128];
__device__ __align__(16) unsigned long long g_epair[MAXE];  // (norm<<32)|src

// ------------------------------ preprocessing ------------------------------

__global__ void k_init(const float* __restrict__ Wm,
                       const float* __restrict__ Wl, int N) {
    int i = blockIdx.x * blockDim.x + threadIdx.x;
    if (i < N) {
        g_deg[i] = 1.0f;   // self-loop weight
        g_cnt[i] = 0;
        g_cursor[i] = 0;
    }
    if (i < 128) g_flag[i] = 0;
    if (i < 6 * 4096)      g_wh[i] = __float2half(Wm[i]);
    else if (i < 7 * 4096) g_wh[i] = __float2half(Wl[i - 6 * 4096]);
}

__global__ void k_edge_deg(const int* __restrict__ ei,
                           const float* __restrict__ ew, int E, int N) {
    int i = blockIdx.x * blockDim.x + threadIdx.x;
    if (i >= E) return;
    int d = ei[E + i];
    if ((unsigned)d >= (unsigned)N) return;
    atomicAdd(&g_deg[d], ew[i]);
    atomicAdd(&g_cnt[d], 1);
}

// single-kernel: dinv/selfnorm + exclusive scan of g_cnt (decoupled lookback).
__global__ void k_scan(int N, int E, int NB) {
    int b = blockIdx.x;
    int t = threadIdx.x;
    int g0 = b * 1024 + 4 * t;

#pragma unroll
    for (int k = 0; k < 4; k++) {
        int g = g0 + k;
        if (g < N) {
            float dg = g_deg[g];
            float r = (dg > 0.0f) ? rsqrtf(dg) : 0.0f;
            g_dinv[g] = r;
            g_selfnorm[g] = r * r;
        }
    }

    int v0 = (g0 + 0 < N) ? g_cnt[g0 + 0] : 0;
    int v1 = (g0 + 1 < N) ? g_cnt[g0 + 1] : 0;
    int v2 = (g0 + 2 < N) ? g_cnt[g0 + 2] : 0;
    int v3 = (g0 + 3 < N) ? g_cnt[g0 + 3] : 0;
    int s = v0 + v1 + v2 + v3;
    int lane = t & 31, wid = t >> 5;
    int incl = s;
#pragma unroll
    for (int o = 1; o < 32; o <<= 1) {
        int x = __shfl_up_sync(0xffffffffu, incl, o);
        if (lane >= o) incl += x;
    }
    __shared__ int wsum[8];
    __shared__ int woff[8];
    __shared__ int sbase;
    if (lane == 31) wsum[wid] = incl;
    __syncthreads();
    if (t == 0) {
        int run = 0;
        for (int i = 0; i < 8; i++) { int x = wsum[i]; woff[i] = run; run += x; }
        int total = run;
        volatile int* vf = (volatile int*)g_flag;
        if (b == 0) {
            g_blkincl[0] = total;
            __threadfence();
            vf[0] = 2;
            sbase = 0;
        } else {
            g_blkagg[b] = total;
            __threadfence();
            vf[b] = 1;
            int acc = 0, p = b - 1;
            while (true) {
                int f;
                do { f = vf[p]; } while (f == 0);
                __threadfence();
                if (f == 2) { acc += g_blkincl[p]; break; }
                acc += g_blkagg[p];
                p--;
            }
            g_blkincl[b] = acc + total;
            __threadfence();
            vf[b] = 2;
            sbase = acc;
        }
        if (b == NB - 1) g_rowoff[N] = E;
    }
    __syncthreads();

    int excl = sbase + woff[wid] + (incl - s);
    if (g0 + 0 < N) g_rowoff[g0 + 0] = excl;
    if (g0 + 1 < N) g_rowoff[g0 + 1] = excl + v0;
    if (g0 + 2 < N) g_rowoff[g0 + 2] = excl + v0 + v1;
    if (g0 + 3 < N) g_rowoff[g0 + 3] = excl + v0 + v1 + v2;
}

__global__ void k_fill(const int* __restrict__ ei,
                       const float* __restrict__ ew, int E, int N) {
    int i = blockIdx.x * blockDim.x + threadIdx.x;
    if (i >= E) return;
    int s = ei[i];
    int d = ei[E + i];
    if ((unsigned)s >= (unsigned)N || (unsigned)d >= (unsigned)N) return;
    float nm = g_dinv[s] * ew[i] * g_dinv[d];
    int pos = g_rowoff[d] + atomicAdd(&g_cursor[d], 1);
    if ((unsigned)pos < (unsigned)MAXE) {
        unsigned long long pr =
            ((unsigned long long)__float_as_uint(nm) << 32) | (unsigned)s;
        g_epair[pos] = pr;
    }
}

// ----------------------- warp-level CSR row aggregation ---------------------
// Returns bias-free aggregate for node w; lane holds feats (2*lane, 2*lane+1).

__device__ __forceinline__ float2 agg_row(const __half2* __restrict__ tin,
                                          int w, int lane) {
    float2 self = __half22float2(tin[(size_t)w * 32 + lane]);
    float sn = g_selfnorm[w];
    float ax = sn * self.x;
    float ay = sn * self.y;
    float bx = 0.f, by = 0.f;

    int j = g_rowoff[w];
    int end = g_rowoff[w + 1];

    if ((j & 1) && j < end) {                    // align to 16B pair boundary
        unsigned long long p = g_epair[j];
        int s = (int)(unsigned)p;
        float m = __uint_as_float((unsigned)(p >> 32));
        float2 v = __half22float2(tin[(size_t)s * 32 + lane]);
        ax += m * v.x; ay += m * v.y;
        j++;
    }
    for (; j + 2 <= end; j += 2) {               // 1 uniform int4 per 2 edges
        int4 pr = *(const int4*)&g_epair[j];
        int s0 = pr.x;
        float m0 = __int_as_float(pr.y);
        int s1 = pr.z;
        float m1 = __int_as_float(pr.w);
        float2 v0 = __half22float2(tin[(size_t)s0 * 32 + lane]);
        float2 v1 = __half22float2(tin[(size_t)s1 * 32 + lane]);
        ax += m0 * v0.x; ay += m0 * v0.y;
        bx += m1 * v1.x; by += m1 * v1.y;
    }
    if (j < end) {                               // tail edge
        unsigned long long p = g_epair[j];
        int s = (int)(unsigned)p;
        float m = __uint_as_float((unsigned)(p >> 32));
        float2 v = __half22float2(tin[(size_t)s * 32 + lane]);
        ax += m * v.x; ay += m * v.y;
    }
    return make_float2(ax + bx, ay + by);
}

// ------------------------- layer-0 transform (SIMT) -------------------------
// C[N,64] = x[N,15] @ W0[15,64], fp32 compute, fp16 store.

__global__ void k_transform0(const float* __restrict__ A,
                             const float* __restrict__ W,
                             __half* __restrict__ C, int N) {
    __shared__ float As[15][68];
    __shared__ float Bs[15][68];
    int t = threadIdx.x;                 // 256 threads
    int n0 = blockIdx.x * 64;

    for (int idx = t; idx < 15 * 64; idx += 256) {
        int k = idx >> 6, f = idx & 63;
        Bs[k][f] = W[idx];
    }
    for (int idx = t; idx < 64 * 15; idx += 256) {
        int node = idx / 15;
        int k = idx % 15;
        int gn = n0 + node;
        As[k][node] = (gn < N) ? A[(size_t)gn * 15 + k] : 0.f;
    }
    __syncthreads();

    int tx = t & 15, ty = t >> 4;
    float acc[4][4];
#pragma unroll
    for (int i = 0; i < 4; i++)
#pragma unroll
        for (int j = 0; j < 4; j++) acc[i][j] = 0.f;

#pragma unroll
    for (int k = 0; k < 15; k++) {
        float4 a = *(const float4*)&As[k][4 * ty];
        float4 b = *(const float4*)&Bs[k][4 * tx];
        float av[4] = {a.x, a.y, a.z, a.w};
        float bv[4] = {b.x, b.y, b.z, b.w};
#pragma unroll
        for (int i = 0; i < 4; i++)
#pragma unroll
            for (int j = 0; j < 4; j++) acc[i][j] += av[i] * bv[j];
    }

#pragma unroll
    for (int i = 0; i < 4; i++) {
        int gn = n0 + 4 * ty + i;
        if (gn < N) {
            __half2 p0 = __floats2half2_rn(acc[i][0], acc[i][1]);
            __half2 p1 = __floats2half2_rn(acc[i][2], acc[i][3]);
            uint2 pk;
            pk.x = *(unsigned*)&p0;
            pk.y = *(unsigned*)&p1;
            *(uint2*)(C + (size_t)gn * 64 + 4 * tx) = pk;
        }
    }
}

// ----------------------------- layer-0 aggregation --------------------------

__global__ void k_agg0(const __half2* __restrict__ tin,
                       const float* __restrict__ bias,
                       __half2* __restrict__ outp, int N) {
    int w = (blockIdx.x * blockDim.x + threadIdx.x) >> 5;
    int lane = threadIdx.x & 31;
    if (w >= N) return;
    float2 a = agg_row(tin, w, lane);
    float2 b = ((const float2*)bias)[lane];
    float ax = fmaxf(a.x + b.x, 0.f);
    float ay = fmaxf(a.y + b.y, 0.f);
    outp[(size_t)w * 32 + lane] = __floats2half2_rn(ax, ay);
}

// ------------------------- fused layer (agg + HMMA) -------------------------
// Block = 256 thr (8 warps) handles 128 nodes: each warp aggregates 16 nodes
// into smem fp16 tile As, then the block does As[128x64] @ W[64x64] via
// mma.m16n8k16 (fp32 accum), bias + act, write out.  hin != outp (ping-pong).

__device__ __forceinline__ void mma16816(float c[4], unsigned a0, unsigned a1,
                                         unsigned a2, unsigned a3,
                                         unsigned b0, unsigned b1) {
    asm volatile(
        "mma.sync.aligned.m16n8k16.row.col.f32.f16.f16.f32 "
        "{%0,%1,%2,%3}, {%4,%5,%6,%7}, {%8,%9}, {%0,%1,%2,%3};\n"
        : "+f"(c[0]), "+f"(c[1]), "+f"(c[2]), "+f"(c[3])
        : "r"(a0), "r"(a1), "r"(a2), "r"(a3), "r"(b0), "r"(b1));
}

template <bool FP16OUT>
__global__ void __launch_bounds__(256) k_layer_fused(
    const __half2* __restrict__ hin,   // [N,64] fp16 (as half2) -- READ ONLY
    const __half* __restrict__ Wh,     // [64,64] fp16, k-major
    const float* __restrict__ bias,
    void* __restrict__ outp, int N, int act)
{
    __shared__ __align__(16) __half As[128 * 72];   // aggregated tile
    __shared__ __align__(16) __half Wt[64 * 72];    // W transposed [n][k]

    int tid = threadIdx.x, lane = tid & 31, wid = tid >> 5;
    int n0 = blockIdx.x * 128;

    for (int i = tid; i < 4096; i += 256) {
        int k = i >> 6, n = i & 63;
        Wt[n * 72 + k] = Wh[i];
    }

    // aggregation: warp handles 16 consecutive nodes
#pragma unroll 1
    for (int i = 0; i < 16; i++) {
        int r = wid * 16 + i;
        int w = n0 + r;
        __half2 hv;
        if (w < N) {
            float2 a = agg_row(hin, w, lane);
            hv = __floats2half2_rn(a.x, a.y);
        } else {
            hv = __floats2half2_rn(0.f, 0.f);
        }
        *(__half2*)&As[r * 72 + lane * 2] = hv;
    }
    __syncthreads();

    // HMMA: 128x64 tile @ 64x64
    int g = lane >> 2, t = lane & 3;
    int m0 = wid * 16;

    float acc[8][4];
#pragma unroll
    for (int i = 0; i < 8; i++)
#pragma unroll
        for (int j = 0; j < 4; j++) acc[i][j] = 0.f;

    const unsigned* As2 = (const unsigned*)As;   // stride 36 uints
    const unsigned* Wt2 = (const unsigned*)Wt;

#pragma unroll
    for (int ks = 0; ks < 4; ks++) {
        int k8 = ks * 8;
        unsigned a0 = As2[(m0 + g) * 36 + k8 + t];
        unsigned a1 = As2[(m0 + g + 8) * 36 + k8 + t];
        unsigned a2 = As2[(m0 + g) * 36 + k8 + 4 + t];
        unsigned a3 = As2[(m0 + g + 8) * 36 + k8 + 4 + t];
#pragma unroll
        for (int nt = 0; nt < 8; nt++) {
            unsigned b0 = Wt2[(nt * 8 + g) * 36 + k8 + t];
            unsigned b1 = Wt2[(nt * 8 + g) * 36 + k8 + 4 + t];
            mma16816(acc[nt], a0, a1, a2, a3, b0, b1);
        }
    }

    // epilogue: bias + act + store
    int r0 = n0 + m0 + g;
    int r1 = r0 + 8;
#pragma unroll
    for (int nt = 0; nt < 8; nt++) {
        float2 bv = ((const float2*)bias)[nt * 4 + t];
        float x0 = acc[nt][0] + bv.x, y0 = acc[nt][1] + bv.y;
        float x1 = acc[nt][2] + bv.x, y1 = acc[nt][3] + bv.y;
        if (act == 1) {
            x0 = fmaxf(x0, 0.f); y0 = fmaxf(y0, 0.f);
            x1 = fmaxf(x1, 0.f); y1 = fmaxf(y1, 0.f);
        } else {
            x0 = 1.0f / (1.0f + __expf(-x0));
            y0 = 1.0f / (1.0f + __expf(-y0));
            x1 = 1.0f / (1.0f + __expf(-x1));
            y1 = 1.0f / (1.0f + __expf(-y1));
        }
        if (FP16OUT) {
            __half2* Cv = (__half2*)outp;
            if (r0 < N) Cv[(size_t)r0 * 32 + nt * 4 + t] = __floats2half2_rn(x0, y0);
            if (r1 < N) Cv[(size_t)r1 * 32 + nt * 4 + t] = __floats2half2_rn(x1, y1);
        } else {
            float2* Cv = (float2*)outp;
            if (r0 < N) Cv[(size_t)r0 * 32 + nt * 4 + t] = make_float2(x0, y0);
            if (r1 < N) Cv[(size_t)r1 * 32 + nt * 4 + t] = make_float2(x1, y1);
        }
    }
}

// --------------------------------- launcher --------------------------------

extern "C" void kernel_launch(void* const* d_in, const int* in_sizes, int n_in,
                              void* d_out, int out_size) {
    const float* x  = (const float*)d_in[0];
    const int*   ei = (const int*)d_in[1];     // int32 (JAX default, x64 off)
    const float* ew = (const float*)d_in[2];
    const float* W0 = (const float*)d_in[3];
    const float* b0 = (const float*)d_in[4];
    const float* Wm = (const float*)d_in[5];
    const float* bm = (const float*)d_in[6];
    const float* Wl = (const float*)d_in[7];
    const float* bl = (const float*)d_in[8];

    int N = in_sizes[0] / 15;
    int E = in_sizes[2];

    __half* hA;
    __half* hB;
    __half* wh;
    cudaGetSymbolAddress((void**)&hA, g_t);
    cudaGetSymbolAddress((void**)&hB, g_hh);
    cudaGetSymbolAddress((void**)&wh, g_wh);

    int NB = (N + 1023) / 1024;

    k_init<<<(N + 255) / 256, 256>>>(Wm, Wl, N);
    k_edge_deg<<<(E + 255) / 256, 256>>>(ei, ew, E, N);
    k_scan<<<NB, 256>>>(N, E, NB);
    k_fill<<<(E + 255) / 256, 256>>>(ei, ew, E, N);

    int gF = (N + 127) / 128;

    // layer 0: hB = relu(agg(x @ W0) + b0)   (hA as temp for t)
    k_transform0<<<(N + 63) / 64, 256>>>(x, W0, hA, N);
    k_agg0<<<(N + 7) / 8, 256>>>((const __half2*)hA, b0, (__half2*)hB, N);

    // fused layers 1..6: ping-pong hB <-> hA
    __half* cur = hB;
    __half* nxt = hA;
    for (int i = 0; i < 6; i++) {
        k_layer_fused<true><<<gF, 256>>>((const __half2*)cur,
                                         wh + (size_t)i * 4096,
                                         bm + (size_t)i * 64, nxt, N, 1);
        __half* tmp = cur; cur = nxt; nxt = tmp;
    }

    // final fused layer + sigmoid -> d_out (fp32)
    k_layer_fused<false><<<gF, 256>>>((const __half2*)cur,
                                      wh + (size_t)6 * 4096, bl, d_out, N, 2);
}

// round 13
// speedup vs baseline: 1.0833x; 1.0833x over previous
#include <cuda_runtime.h>
#include <cuda_fp16.h>
#include <cstdint>

// ---------------------------------------------------------------------------
// GCNEncoder: 8-layer GCN, N=100000, E=1.6M, F=15->64(x7)->64
// Round-9 architecture (best: 458us): separate HMMA transform + warp/node agg.
// Round 13 change: agg raises memory-level parallelism -- 4-edge unroll
// (2 independent int4 pair loads + 4 independent gathers) + grid-stride
// persistent blocks. Everything else identical to round 9.
// edge_index is int32 on device (JAX default, x64 disabled).
// ---------------------------------------------------------------------------

#define MAXN 131072
#define MAXE 1700000

__device__ __half g_t[MAXN * 64];        // transformed features (fp16)
__device__ __half g_hh[MAXN * 64];       // activations (fp16)
__device__ __half g_wh[7 * 4096];        // fp16 weights: Wm[0..5], Wl
__device__ float  g_deg[MAXN];
__device__ float  g_dinv[MAXN];
__device__ float  g_selfnorm[MAXN];
__device__ int    g_cnt[MAXN];
__device__ int    g_cursor[MAXN];
__device__ int    g_rowoff[MAXN + 1];
__device__ int    g_blkagg[128];
__device__ int    g_blkincl[128];
__device__ int    g_flag[128];
__device__ __align__(16) unsigned long long g_epair[MAXE];  // (norm<<32)|src

// ------------------------------ preprocessing ------------------------------

__global__ void k_init(const float* __restrict__ Wm,
                       const float* __restrict__ Wl, int N) {
    int i = blockIdx.x * blockDim.x + threadIdx.x;
    if (i < N) {
        g_deg[i] = 1.0f;   // self-loop weight
        g_cnt[i] = 0;
        g_cursor[i] = 0;
    }
    if (i < 128) g_flag[i] = 0;
    if (i < 6 * 4096)      g_wh[i] = __float2half(Wm[i]);
    else if (i < 7 * 4096) g_wh[i] = __float2half(Wl[i - 6 * 4096]);
}

__global__ void k_edge_deg(const int* __restrict__ ei,
                           const float* __restrict__ ew, int E, int N) {
    int i = blockIdx.x * blockDim.x + threadIdx.x;
    if (i >= E) return;
    int d = ei[E + i];
    if ((unsigned)d >= (unsigned)N) return;
    atomicAdd(&g_deg[d], ew[i]);
    atomicAdd(&g_cnt[d], 1);
}

// single-kernel: dinv/selfnorm + exclusive scan of g_cnt (decoupled lookback).
__global__ void k_scan(int N, int E, int NB) {
    int b = blockIdx.x;
    int t = threadIdx.x;
    int g0 = b * 1024 + 4 * t;

#pragma unroll
    for (int k = 0; k < 4; k++) {
        int g = g0 + k;
        if (g < N) {
            float dg = g_deg[g];
            float r = (dg > 0.0f) ? rsqrtf(dg) : 0.0f;
            g_dinv[g] = r;
            g_selfnorm[g] = r * r;
        }
    }

    int v0 = (g0 + 0 < N) ? g_cnt[g0 + 0] : 0;
    int v1 = (g0 + 1 < N) ? g_cnt[g0 + 1] : 0;
    int v2 = (g0 + 2 < N) ? g_cnt[g0 + 2] : 0;
    int v3 = (g0 + 3 < N) ? g_cnt[g0 + 3] : 0;
    int s = v0 + v1 + v2 + v3;
    int lane = t & 31, wid = t >> 5;
    int incl = s;
#pragma unroll
    for (int o = 1; o < 32; o <<= 1) {
        int x = __shfl_up_sync(0xffffffffu, incl, o);
        if (lane >= o) incl += x;
    }
    __shared__ int wsum[8];
    __shared__ int woff[8];
    __shared__ int sbase;
    if (lane == 31) wsum[wid] = incl;
    __syncthreads();
    if (t == 0) {
        int run = 0;
        for (int i = 0; i < 8; i++) { int x = wsum[i]; woff[i] = run; run += x; }
        int total = run;
        volatile int* vf = (volatile int*)g_flag;
        if (b == 0) {
            g_blkincl[0] = total;
            __threadfence();
            vf[0] = 2;
            sbase = 0;
        } else {
            g_blkagg[b] = total;
            __threadfence();
            vf[b] = 1;
            int acc = 0, p = b - 1;
            while (true) {
                int f;
                do { f = vf[p]; } while (f == 0);
                __threadfence();
                if (f == 2) { acc += g_blkincl[p]; break; }
                acc += g_blkagg[p];
                p--;
            }
            g_blkincl[b] = acc + total;
            __threadfence();
            vf[b] = 2;
            sbase = acc;
        }
        if (b == NB - 1) g_rowoff[N] = E;
    }
    __syncthreads();

    int excl = sbase + woff[wid] + (incl - s);
    if (g0 + 0 < N) g_rowoff[g0 + 0] = excl;
    if (g0 + 1 < N) g_rowoff[g0 + 1] = excl + v0;
    if (g0 + 2 < N) g_rowoff[g0 + 2] = excl + v0 + v1;
    if (g0 + 3 < N) g_rowoff[g0 + 3] = excl + v0 + v1 + v2;
}

__global__ void k_fill(const int* __restrict__ ei,
                       const float* __restrict__ ew, int E, int N) {
    int i = blockIdx.x * blockDim.x + threadIdx.x;
    if (i >= E) return;
    int s = ei[i];
    int d = ei[E + i];
    if ((unsigned)s >= (unsigned)N || (unsigned)d >= (unsigned)N) return;
    float nm = g_dinv[s] * ew[i] * g_dinv[d];
    int pos = g_rowoff[d] + atomicAdd(&g_cursor[d], 1);
    if ((unsigned)pos < (unsigned)MAXE) {
        unsigned long long pr =
            ((unsigned long long)__float_as_uint(nm) << 32) | (unsigned)s;
        g_epair[pos] = pr;
    }
}

// ------------------------- layer-0 transform (SIMT) -------------------------
// C[N,64] = x[N,15] @ W0[15,64], fp32 compute, fp16 store.

__global__ void k_transform0(const float* __restrict__ A,
                             const float* __restrict__ W,
                             __half* __restrict__ C, int N) {
    __shared__ float As[15][68];
    __shared__ float Bs[15][68];
    int t = threadIdx.x;                 // 256 threads
    int n0 = blockIdx.x * 64;

    for (int idx = t; idx < 15 * 64; idx += 256) {
        int k = idx >> 6, f = idx & 63;
        Bs[k][f] = W[idx];
    }
    for (int idx = t; idx < 64 * 15; idx += 256) {
        int node = idx / 15;
        int k = idx % 15;
        int gn = n0 + node;
        As[k][node] = (gn < N) ? A[(size_t)gn * 15 + k] : 0.f;
    }
    __syncthreads();

    int tx = t & 15, ty = t >> 4;
    float acc[4][4];
#pragma unroll
    for (int i = 0; i < 4; i++)
#pragma unroll
        for (int j = 0; j < 4; j++) acc[i][j] = 0.f;

#pragma unroll
    for (int k = 0; k < 15; k++) {
        float4 a = *(const float4*)&As[k][4 * ty];
        float4 b = *(const float4*)&Bs[k][4 * tx];
        float av[4] = {a.x, a.y, a.z, a.w};
        float bv[4] = {b.x, b.y, b.z, b.w};
#pragma unroll
        for (int i = 0; i < 4; i++)
#pragma unroll
            for (int j = 0; j < 4; j++) acc[i][j] += av[i] * bv[j];
    }

#pragma unroll
    for (int i = 0; i < 4; i++) {
        int gn = n0 + 4 * ty + i;
        if (gn < N) {
            __half2 p0 = __floats2half2_rn(acc[i][0], acc[i][1]);
            __half2 p1 = __floats2half2_rn(acc[i][2], acc[i][3]);
            uint2 pk;
            pk.x = *(unsigned*)&p0;
            pk.y = *(unsigned*)&p1;
            *(uint2*)(C + (size_t)gn * 64 + 4 * tx) = pk;
        }
    }
}

// ---------------------- mid/final transform (tensor core) -------------------
// C[N,64] = A[N,64] @ W[64,64]; A,W fp16, fp32 accum via mma.m16n8k16.

__device__ __forceinline__ void mma16816(float c[4], unsigned a0, unsigned a1,
                                         unsigned a2, unsigned a3,
                                         unsigned b0, unsigned b1) {
    asm volatile(
        "mma.sync.aligned.m16n8k16.row.col.f32.f16.f16.f32 "
        "{%0,%1,%2,%3}, {%4,%5,%6,%7}, {%8,%9}, {%0,%1,%2,%3};\n"
        : "+f"(c[0]), "+f"(c[1]), "+f"(c[2]), "+f"(c[3])
        : "r"(a0), "r"(a1), "r"(a2), "r"(a3), "r"(b0), "r"(b1));
}

__global__ void __launch_bounds__(256) k_transform_tc(
    const __half* __restrict__ A,      // [N,64] fp16
    const __half* __restrict__ Wh,     // [64,64] fp16, k-major
    __half* __restrict__ C, int N)
{
    __shared__ __align__(16) __half As[128 * 72];   // row stride 72 halves
    __shared__ __align__(16) __half Wt[64 * 72];    // transposed [n][k]

    int tid = threadIdx.x;
    int n0 = blockIdx.x * 128;

    for (int i = tid; i < 4096; i += 256) {
        int k = i >> 6, n = i & 63;
        Wt[n * 72 + k] = Wh[i];
    }
    {
        const uint4* Ag = (const uint4*)A;   // 8 uint4 per 64-half row
#pragma unroll
        for (int r4 = 0; r4 < 4; r4++) {
            int q = tid + 256 * r4;          // 0..1023
            int r = q >> 3, u = q & 7;
            int gr = n0 + r;
            uint4 v = (gr < N) ? Ag[(size_t)gr * 8 + u]
                               : make_uint4(0u, 0u, 0u, 0u);
            *(uint4*)&As[r * 72 + u * 8] = v;
        }
    }
    __syncthreads();

    int lane = tid & 31, warp = tid >> 5;
    int g = lane >> 2, t = lane & 3;
    int m0 = warp * 16;

    float acc[8][4];
#pragma unroll
    for (int i = 0; i < 8; i++)
#pragma unroll
        for (int j = 0; j < 4; j++) acc[i][j] = 0.f;

    const unsigned* As2 = (const unsigned*)As;   // stride 36 uints
    const unsigned* Wt2 = (const unsigned*)Wt;

#pragma unroll
    for (int ks = 0; ks < 4; ks++) {
        int k8 = ks * 8;                         // k offset in uints
        unsigned a0 = As2[(m0 + g) * 36 + k8 + t];
        unsigned a1 = As2[(m0 + g + 8) * 36 + k8 + t];
        unsigned a2 = As2[(m0 + g) * 36 + k8 + 4 + t];
        unsigned a3 = As2[(m0 + g + 8) * 36 + k8 + 4 + t];
#pragma unroll
        for (int nt = 0; nt < 8; nt++) {
            unsigned b0 = Wt2[(nt * 8 + g) * 36 + k8 + t];
            unsigned b1 = Wt2[(nt * 8 + g) * 36 + k8 + 4 + t];
            mma16816(acc[nt], a0, a1, a2, a3, b0, b1);
        }
    }

    __half2* Cv = (__half2*)C;                   // 32 half2 per row
    int r0 = n0 + m0 + g;
    int r1 = r0 + 8;
#pragma unroll
    for (int nt = 0; nt < 8; nt++) {
        if (r0 < N) Cv[(size_t)r0 * 32 + nt * 4 + t] =
            __floats2half2_rn(acc[nt][0], acc[nt][1]);
        if (r1 < N) Cv[(size_t)r1 * 32 + nt * 4 + t] =
            __floats2half2_rn(acc[nt][2], acc[nt][3]);
    }
}

// ------------------------------- aggregation -------------------------------
// Grid-stride persistent blocks; one warp per node; lane holds 2 features.
// 4-edge unroll: 2 independent int4 pair loads + 4 independent gathers
// per iteration (MLP ~4-6). fp32 accumulation.

template <bool FP16OUT>
__global__ void __launch_bounds__(256) k_agg(
    const __half2* __restrict__ tin,
    const float* __restrict__ bias,
    void* __restrict__ outp, int N, int act)
{
    int lane = threadIdx.x & 31;
    int wid = threadIdx.x >> 5;
    int nW = gridDim.x * 8;
    float2 bv = ((const float2*)bias)[lane];

    for (int w = blockIdx.x * 8 + wid; w < N; w += nW) {
        float2 self = __half22float2(tin[(size_t)w * 32 + lane]);
        float sn = g_selfnorm[w];
        float ax = sn * self.x;
        float ay = sn * self.y;
        float bx = 0.f, by = 0.f;
        float cx = 0.f, cy = 0.f;
        float dx = 0.f, dy = 0.f;

        int j = g_rowoff[w];
        int end = g_rowoff[w + 1];

        if ((j & 1) && j < end) {            // align to 16B pair boundary
            unsigned long long p = g_epair[j];
            int s = (int)(unsigned)p;
            float m = __uint_as_float((unsigned)(p >> 32));
            float2 v = __half22float2(tin[(size_t)s * 32 + lane]);
            ax += m * v.x; ay += m * v.y;
            j++;
        }
        // main: 4 edges per iter, 2 independent int4 + 4 independent gathers
        for (; j + 4 <= end; j += 4) {
            int4 p0 = *(const int4*)&g_epair[j];
            int4 p1 = *(const int4*)&g_epair[j + 2];
            float2 v0 = __half22float2(tin[(size_t)p0.x * 32 + lane]);
            float2 v1 = __half22float2(tin[(size_t)p0.z * 32 + lane]);
            float2 v2 = __half22float2(tin[(size_t)p1.x * 32 + lane]);
            float2 v3 = __half22float2(tin[(size_t)p1.z * 32 + lane]);
            float m0 = __int_as_float(p0.y);
            float m1 = __int_as_float(p0.w);
            float m2 = __int_as_float(p1.y);
            float m3 = __int_as_float(p1.w);
            ax += m0 * v0.x; ay += m0 * v0.y;
            bx += m1 * v1.x; by += m1 * v1.y;
            cx += m2 * v2.x; cy += m2 * v2.y;
            dx += m3 * v3.x; dy += m3 * v3.y;
        }
        if (j + 2 <= end) {                  // 2-edge chunk
            int4 p0 = *(const int4*)&g_epair[j];
            float2 v0 = __half22float2(tin[(size_t)p0.x * 32 + lane]);
            float2 v1 = __half22float2(tin[(size_t)p0.z * 32 + lane]);
            float m0 = __int_as_float(p0.y);
            float m1 = __int_as_float(p0.w);
            ax += m0 * v0.x; ay += m0 * v0.y;
            bx += m1 * v1.x; by += m1 * v1.y;
            j += 2;
        }
        if (j < end) {                       // tail edge
            unsigned long long p = g_epair[j];
            int s = (int)(unsigned)p;
            float m = __uint_as_float((unsigned)(p >> 32));
            float2 v = __half22float2(tin[(size_t)s * 32 + lane]);
            ax += m * v.x; ay += m * v.y;
        }

        float ox = (ax + bx) + (cx + dx) + bv.x;
        float oy = (ay + by) + (cy + dy) + bv.y;
        if (act == 1) {
            ox = fmaxf(ox, 0.f);
            oy = fmaxf(oy, 0.f);
        } else {
            ox = 1.0f / (1.0f + __expf(-ox));
            oy = 1.0f / (1.0f + __expf(-oy));
        }
        if (FP16OUT) {
            ((__half2*)outp)[(size_t)w * 32 + lane] = __floats2half2_rn(ox, oy);
        } else {
            ((float2*)outp)[(size_t)w * 32 + lane] = make_float2(ox, oy);
        }
    }
}

// --------------------------------- launcher --------------------------------

extern "C" void kernel_launch(void* const* d_in, const int* in_sizes, int n_in,
                              void* d_out, int out_size) {
    const float* x  = (const float*)d_in[0];
    const int*   ei = (const int*)d_in[1];     // int32 (JAX default, x64 off)
    const float* ew = (const float*)d_in[2];
    const float* W0 = (const float*)d_in[3];
    const float* b0 = (const float*)d_in[4];
    const float* Wm = (const float*)d_in[5];
    const float* bm = (const float*)d_in[6];
    const float* Wl = (const float*)d_in[7];
    const float* bl = (const float*)d_in[8];

    int N = in_sizes[0] / 15;
    int E = in_sizes[2];

    __half* t;
    __half* h;
    __half* wh;
    cudaGetSymbolAddress((void**)&t, g_t);
    cudaGetSymbolAddress((void**)&h, g_hh);
    cudaGetSymbolAddress((void**)&wh, g_wh);

    int NB = (N + 1023) / 1024;

    k_init<<<(N + 255) / 256, 256>>>(Wm, Wl, N);
    k_edge_deg<<<(E + 255) / 256, 256>>>(ei, ew, E, N);
    k_scan<<<NB, 256>>>(N, E, NB);
    k_fill<<<(E + 255) / 256, 256>>>(ei, ew, E, N);

    int gT = (N + 127) / 128;
    const int gA = 1184;   // persistent grid-stride (8 blocks/SM)

    // layer 0: h = relu(agg(x @ W0) + b0)
    k_transform0<<<(N + 63) / 64, 256>>>(x, W0, t, N);
    k_agg<true><<<gA, 256>>>((const __half2*)t, b0, h, N, 1);

    // middle layers 1..6 (tensor-core transform)
    for (int i = 0; i < 6; i++) {
        k_transform_tc<<<gT, 256>>>(h, wh + (size_t)i * 4096, t, N);
        k_agg<true><<<gA, 256>>>((const __half2*)t, bm + (size_t)i * 64, h, N, 1);
    }

    // final layer + sigmoid -> d_out (fp32)
    k_transform_tc<<<gT, 256>>>(h, wh + (size_t)6 * 4096, t, N);
    k_agg<false><<<gA, 256>>>((const __half2*)t, bl, d_out, N, 2);
}

// round 14
// speedup vs baseline: 1.3697x; 1.2644x over previous
#include <cuda_runtime.h>
#include <cuda_fp16.h>
#include <cstdint>

// ---------------------------------------------------------------------------
// GCNEncoder: 8-layer GCN, N=100000, E=1.6M, F=15->64(x7)->64
// Round-9 architecture (best: 457.8us) EXACTLY, plus one change:
// k_edge_deg uses ONE 64-bit fixed-point atomic per edge
// ((cnt<<40) | w*2^24) instead of two (float deg + int cnt).
// h fp16; mid/final transforms = HMMA (fp32 accum); agg = warp/node CSR
// gather over interleaved (src,norm) pairs (frozen round-9 inner loop).
// edge_index is int32 on device (JAX default, x64 disabled).
// ---------------------------------------------------------------------------

#define MAXN 131072
#define MAXE 1700000

__device__ __half g_t[MAXN * 64];        // transformed features (fp16)
__device__ __half g_hh[MAXN * 64];       // activations (fp16)
__device__ __half g_wh[7 * 4096];        // fp16 weights: Wm[0..5], Wl
__device__ unsigned long long g_degcnt[MAXN];  // (cnt<<40)|deg_fp24
__device__ float  g_dinv[MAXN];
__device__ float  g_selfnorm[MAXN];
__device__ int    g_cursor[MAXN];
__device__ int    g_rowoff[MAXN + 1];
__device__ int    g_blkagg[128];
__device__ int    g_blkincl[128];
__device__ int    g_flag[128];
__device__ __align__(16) unsigned long long g_epair[MAXE];  // (norm<<32)|src

// ------------------------------ preprocessing ------------------------------

__global__ void k_init(const float* __restrict__ Wm,
                       const float* __restrict__ Wl, int N) {
    int i = blockIdx.x * blockDim.x + threadIdx.x;
    if (i < N) {
        g_degcnt[i] = 16777216ULL;   // deg = 1.0 (self-loop), cnt = 0
        g_cursor[i] = 0;
    }
    if (i < 128) g_flag[i] = 0;
    if (i < 6 * 4096)      g_wh[i] = __float2half(Wm[i]);
    else if (i < 7 * 4096) g_wh[i] = __float2half(Wl[i - 6 * 4096]);
}

__global__ void k_edge_deg(const int* __restrict__ ei,
                           const float* __restrict__ ew, int E, int N) {
    int i = blockIdx.x * blockDim.x + threadIdx.x;
    if (i >= E) return;
    int d = ei[E + i];
    if ((unsigned)d >= (unsigned)N) return;
    // fixed-point weight (2^-24 quantum) + count in one 64-bit atomic
    unsigned wfp = (unsigned)__float2uint_rn(ew[i] * 16777216.0f);
    atomicAdd(&g_degcnt[d], (1ULL << 40) | (unsigned long long)wfp);
}

// single-kernel: dinv/selfnorm + exclusive scan of counts (decoupled lookback).
__global__ void k_scan(int N, int E, int NB) {
    int b = blockIdx.x;
    int t = threadIdx.x;
    int g0 = b * 1024 + 4 * t;

    int vc[4];
#pragma unroll
    for (int k = 0; k < 4; k++) {
        int g = g0 + k;
        if (g < N) {
            unsigned long long p = g_degcnt[g];
            float dg = (float)(p & 0xFFFFFFFFFFULL) * 5.9604644775390625e-8f; // 2^-24
            float r = (dg > 0.0f) ? rsqrtf(dg) : 0.0f;
            g_dinv[g] = r;
            g_selfnorm[g] = r * r;
            vc[k] = (int)(p >> 40);
        } else {
            vc[k] = 0;
        }
    }

    int v0 = vc[0], v1 = vc[1], v2 = vc[2], v3 = vc[3];
    int s = v0 + v1 + v2 + v3;
    int lane = t & 31, wid = t >> 5;
    int incl = s;
#pragma unroll
    for (int o = 1; o < 32; o <<= 1) {
        int x = __shfl_up_sync(0xffffffffu, incl, o);
        if (lane >= o) incl += x;
    }
    __shared__ int wsum[8];
    __shared__ int woff[8];
    __shared__ int sbase;
    if (lane == 31) wsum[wid] = incl;
    __syncthreads();
    if (t == 0) {
        int run = 0;
        for (int i = 0; i < 8; i++) { int x = wsum[i]; woff[i] = run; run += x; }
        int total = run;
        volatile int* vf = (volatile int*)g_flag;
        if (b == 0) {
            g_blkincl[0] = total;
            __threadfence();
            vf[0] = 2;
            sbase = 0;
        } else {
            g_blkagg[b] = total;
            __threadfence();
            vf[b] = 1;
            int acc = 0, p = b - 1;
            while (true) {
                int f;
                do { f = vf[p]; } while (f == 0);
                __threadfence();
                if (f == 2) { acc += g_blkincl[p]; break; }
                acc += g_blkagg[p];
                p--;
            }
            g_blkincl[b] = acc + total;
            __threadfence();
            vf[b] = 2;
            sbase = acc;
        }
        if (b == NB - 1) g_rowoff[N] = E;
    }
    __syncthreads();

    int excl = sbase + woff[wid] + (incl - s);
    if (g0 + 0 < N) g_rowoff[g0 + 0] = excl;
    if (g0 + 1 < N) g_rowoff[g0 + 1] = excl + v0;
    if (g0 + 2 < N) g_rowoff[g0 + 2] = excl + v0 + v1;
    if (g0 + 3 < N) g_rowoff[g0 + 3] = excl + v0 + v1 + v2;
}

__global__ void k_fill(const int* __restrict__ ei,
                       const float* __restrict__ ew, int E, int N) {
    int i = blockIdx.x * blockDim.x + threadIdx.x;
    if (i >= E) return;
    int s = ei[i];
    int d = ei[E + i];
    if ((unsigned)s >= (unsigned)N || (unsigned)d >= (unsigned)N) return;
    float nm = g_dinv[s] * ew[i] * g_dinv[d];
    int pos = g_rowoff[d] + atomicAdd(&g_cursor[d], 1);
    if ((unsigned)pos < (unsigned)MAXE) {
        unsigned long long pr =
            ((unsigned long long)__float_as_uint(nm) << 32) | (unsigned)s;
        g_epair[pos] = pr;
    }
}

// ------------------------- layer-0 transform (SIMT) -------------------------
// C[N,64] = x[N,15] @ W0[15,64], fp32 compute, fp16 store.

__global__ void k_transform0(const float* __restrict__ A,
                             const float* __restrict__ W,
                             __half* __restrict__ C, int N) {
    __shared__ float As[15][68];
    __shared__ float Bs[15][68];
    int t = threadIdx.x;                 // 256 threads
    int n0 = blockIdx.x * 64;

    for (int idx = t; idx < 15 * 64; idx += 256) {
        int k = idx >> 6, f = idx & 63;
        Bs[k][f] = W[idx];
    }
    for (int idx = t; idx < 64 * 15; idx += 256) {
        int node = idx / 15;
        int k = idx % 15;
        int gn = n0 + node;
        As[k][node] = (gn < N) ? A[(size_t)gn * 15 + k] : 0.f;
    }
    __syncthreads();

    int tx = t & 15, ty = t >> 4;
    float acc[4][4];
#pragma unroll
    for (int i = 0; i < 4; i++)
#pragma unroll
        for (int j = 0; j < 4; j++) acc[i][j] = 0.f;

#pragma unroll
    for (int k = 0; k < 15; k++) {
        float4 a = *(const float4*)&As[k][4 * ty];
        float4 b = *(const float4*)&Bs[k][4 * tx];
        float av[4] = {a.x, a.y, a.z, a.w};
        float bv[4] = {b.x, b.y, b.z, b.w};
#pragma unroll
        for (int i = 0; i < 4; i++)
#pragma unroll
            for (int j = 0; j < 4; j++) acc[i][j] += av[i] * bv[j];
    }

#pragma unroll
    for (int i = 0; i < 4; i++) {
        int gn = n0 + 4 * ty + i;
        if (gn < N) {
            __half2 p0 = __floats2half2_rn(acc[i][0], acc[i][1]);
            __half2 p1 = __floats2half2_rn(acc[i][2], acc[i][3]);
            uint2 pk;
            pk.x = *(unsigned*)&p0;
            pk.y = *(unsigned*)&p1;
            *(uint2*)(C + (size_t)gn * 64 + 4 * tx) = pk;
        }
    }
}

// ---------------------- mid/final transform (tensor core) -------------------
// C[N,64] = A[N,64] @ W[64,64]; A,W fp16, fp32 accum via mma.m16n8k16.

__device__ __forceinline__ void mma16816(float c[4], unsigned a0, unsigned a1,
                                         unsigned a2, unsigned a3,
                                         unsigned b0, unsigned b1) {
    asm volatile(
        "mma.sync.aligned.m16n8k16.row.col.f32.f16.f16.f32 "
        "{%0,%1,%2,%3}, {%4,%5,%6,%7}, {%8,%9}, {%0,%1,%2,%3};\n"
        : "+f"(c[0]), "+f"(c[1]), "+f"(c[2]), "+f"(c[3])
        : "r"(a0), "r"(a1), "r"(a2), "r"(a3), "r"(b0), "r"(b1));
}

__global__ void __launch_bounds__(256) k_transform_tc(
    const __half* __restrict__ A,      // [N,64] fp16
    const __half* __restrict__ Wh,     // [64,64] fp16, k-major
    __half* __restrict__ C, int N)
{
    __shared__ __align__(16) __half As[128 * 72];   // row stride 72 halves
    __shared__ __align__(16) __half Wt[64 * 72];    // transposed [n][k]

    int tid = threadIdx.x;
    int n0 = blockIdx.x * 128;

    for (int i = tid; i < 4096; i += 256) {
        int k = i >> 6, n = i & 63;
        Wt[n * 72 + k] = Wh[i];
    }
    {
        const uint4* Ag = (const uint4*)A;   // 8 uint4 per 64-half row
#pragma unroll
        for (int r4 = 0; r4 < 4; r4++) {
            int q = tid + 256 * r4;          // 0..1023
            int r = q >> 3, u = q & 7;
            int gr = n0 + r;
            uint4 v = (gr < N) ? Ag[(size_t)gr * 8 + u]
                               : make_uint4(0u, 0u, 0u, 0u);
            *(uint4*)&As[r * 72 + u * 8] = v;
        }
    }
    __syncthreads();

    int lane = tid & 31, warp = tid >> 5;
    int g = lane >> 2, t = lane & 3;
    int m0 = warp * 16;

    float acc[8][4];
#pragma unroll
    for (int i = 0; i < 8; i++)
#pragma unroll
        for (int j = 0; j < 4; j++) acc[i][j] = 0.f;

    const unsigned* As2 = (const unsigned*)As;   // stride 36 uints
    const unsigned* Wt2 = (const unsigned*)Wt;

#pragma unroll
    for (int ks = 0; ks < 4; ks++) {
        int k8 = ks * 8;                         // k offset in uints
        unsigned a0 = As2[(m0 + g) * 36 + k8 + t];
        unsigned a1 = As2[(m0 + g + 8) * 36 + k8 + t];
        unsigned a2 = As2[(m0 + g) * 36 + k8 + 4 + t];
        unsigned a3 = As2[(m0 + g + 8) * 36 + k8 + 4 + t];
#pragma unroll
        for (int nt = 0; nt < 8; nt++) {
            unsigned b0 = Wt2[(nt * 8 + g) * 36 + k8 + t];
            unsigned b1 = Wt2[(nt * 8 + g) * 36 + k8 + 4 + t];
            mma16816(acc[nt], a0, a1, a2, a3, b0, b1);
        }
    }

    __half2* Cv = (__half2*)C;                   // 32 half2 per row
    int r0 = n0 + m0 + g;
    int r1 = r0 + 8;
#pragma unroll
    for (int nt = 0; nt < 8; nt++) {
        if (r0 < N) Cv[(size_t)r0 * 32 + nt * 4 + t] =
            __floats2half2_rn(acc[nt][0], acc[nt][1]);
        if (r1 < N) Cv[(size_t)r1 * 32 + nt * 4 + t] =
            __floats2half2_rn(acc[nt][2], acc[nt][3]);
    }
}

// ------------------------------- aggregation -------------------------------
// FROZEN round-9 form: one warp per node; lane holds 2 features as one half2;
// fp32 accumulation; interleaved pairs, 1 uniform int4 per 2 edges.

template <bool FP16OUT>
__global__ void k_agg(const __half2* __restrict__ tin,
                      const float* __restrict__ bias,
                      void* __restrict__ outp, int N, int act) {
    int w = (blockIdx.x * blockDim.x + threadIdx.x) >> 5;
    int lane = threadIdx.x & 31;
    if (w >= N) return;

    float2 self = __half22float2(tin[(size_t)w * 32 + lane]);
    float sn = g_selfnorm[w];
    float ax = sn * self.x;
    float ay = sn * self.y;
    float bx = 0.f, by = 0.f;

    int beg = g_rowoff[w];
    int end = g_rowoff[w + 1];
    int j = beg;

    // peel one edge if start is odd (int4 needs 16B = 2-pair alignment)
    if ((j & 1) && j < end) {
        unsigned long long p = g_epair[j];
        int s = (int)(unsigned)p;
        float m = __uint_as_float((unsigned)(p >> 32));
        float2 v = __half22float2(tin[(size_t)s * 32 + lane]);
        ax += m * v.x; ay += m * v.y;
        j++;
    }
    // 2 edges per uniform int4
    for (; j + 2 <= end; j += 2) {
        int4 pr = *(const int4*)&g_epair[j];
        int s0 = pr.x;
        float m0 = __int_as_float(pr.y);
        int s1 = pr.z;
        float m1 = __int_as_float(pr.w);
        float2 v0 = __half22float2(tin[(size_t)s0 * 32 + lane]);
        float2 v1 = __half22float2(tin[(size_t)s1 * 32 + lane]);
        ax += m0 * v0.x; ay += m0 * v0.y;
        bx += m1 * v1.x; by += m1 * v1.y;
    }
    // tail edge
    if (j < end) {
        unsigned long long p = g_epair[j];
        int s = (int)(unsigned)p;
        float m = __uint_as_float((unsigned)(p >> 32));
        float2 v = __half22float2(tin[(size_t)s * 32 + lane]);
        ax += m * v.x; ay += m * v.y;
    }
    ax += bx; ay += by;

    float2 b = ((const float2*)bias)[lane];
    ax += b.x; ay += b.y;
    if (act == 1) {
        ax = fmaxf(ax, 0.f);
        ay = fmaxf(ay, 0.f);
    } else {
        ax = 1.0f / (1.0f + __expf(-ax));
        ay = 1.0f / (1.0f + __expf(-ay));
    }
    if (FP16OUT) {
        ((__half2*)outp)[(size_t)w * 32 + lane] = __floats2half2_rn(ax, ay);
    } else {
        ((float2*)outp)[(size_t)w * 32 + lane] = make_float2(ax, ay);
    }
}

// --------------------------------- launcher --------------------------------

extern "C" void kernel_launch(void* const* d_in, const int* in_sizes, int n_in,
                              void* d_out, int out_size) {
    const float* x  = (const float*)d_in[0];
    const int*   ei = (const int*)d_in[1];     // int32 (JAX default, x64 off)
    const float* ew = (const float*)d_in[2];
    const float* W0 = (const float*)d_in[3];
    const float* b0 = (const float*)d_in[4];
    const float* Wm = (const float*)d_in[5];
    const float* bm = (const float*)d_in[6];
    const float* Wl = (const float*)d_in[7];
    const float* bl = (const float*)d_in[8];

    int N = in_sizes[0] / 15;
    int E = in_sizes[2];

    __half* t;
    __half* h;
    __half* wh;
    cudaGetSymbolAddress((void**)&t, g_t);
    cudaGetSymbolAddress((void**)&h, g_hh);
    cudaGetSymbolAddress((void**)&wh, g_wh);

    int NB = (N + 1023) / 1024;

    k_init<<<(N + 255) / 256, 256>>>(Wm, Wl, N);
    k_edge_deg<<<(E + 255) / 256, 256>>>(ei, ew, E, N);
    k_scan<<<NB, 256>>>(N, E, NB);
    k_fill<<<(E + 255) / 256, 256>>>(ei, ew, E, N);

    int gT = (N + 127) / 128;
    int gA = (N + 7) / 8;

    // layer 0: h = relu(agg(x @ W0) + b0)
    k_transform0<<<(N + 63) / 64, 256>>>(x, W0, t, N);
    k_agg<true><<<gA, 256>>>((const __half2*)t, b0, h, N, 1);

    // middle layers 1..6 (tensor-core transform)
    for (int i = 0; i < 6; i++) {
        k_transform_tc<<<gT, 256>>>(h, wh + (size_t)i * 4096, t, N);
        k_agg<true><<<gA, 256>>>((const __half2*)t, bm + (size_t)i * 64, h, N, 1);
    }

    // final layer + sigmoid -> d_out (fp32)
    k_transform_tc<<<gT, 256>>>(h, wh + (size_t)6 * 4096, t, N);
    k_agg<false><<<gA, 256>>>((const __half2*)t, bl, d_out, N, 2);
}

// round 15
// speedup vs baseline: 1.3715x; 1.0013x over previous
#include <cuda_runtime.h>
#include <cuda_fp16.h>
#include <cstdint>

// ---------------------------------------------------------------------------
// GCNEncoder: 8-layer GCN, N=100000, E=1.6M, F=15->64(x7)->64
// Round-14 platform (450us) + two structural changes:
//  1) k_transform0 overlapped with the preprocessing chain via stream
//     fork/join (capture-legal: event fork from legacy stream, join before
//     k_agg0).
//  2) k_fill stores m' = w*dinv[src] only; agg multiplies by dinv[dst] in
//     the epilogue (removes 1.6M random gathers from fill; same math).
// h fp16; mid/final transforms = HMMA (fp32 accum); agg loop FROZEN (R9).
// edge_index is int32 on device (JAX default, x64 disabled).
// ---------------------------------------------------------------------------

#define MAXN 131072
#define MAXE 1700000

__device__ __half g_t[MAXN * 64];        // transformed features (fp16)
__device__ __half g_hh[MAXN * 64];       // activations (fp16)
__device__ __half g_wh[7 * 4096];        // fp16 weights: Wm[0..5], Wl
__device__ unsigned long long g_degcnt[MAXN];  // (cnt<<40)|deg_fp24
__device__ float  g_dinv[MAXN];
__device__ int    g_cursor[MAXN];
__device__ int    g_rowoff[MAXN + 1];
__device__ int    g_blkagg[128];
__device__ int    g_blkincl[128];
__device__ int    g_flag[128];
__device__ __align__(16) unsigned long long g_epair[MAXE];  // (m'<<32)|src

// ------------------------------ preprocessing ------------------------------

__global__ void k_init(const float* __restrict__ Wm,
                       const float* __restrict__ Wl, int N) {
    int i = blockIdx.x * blockDim.x + threadIdx.x;
    if (i < N) {
        g_degcnt[i] = 16777216ULL;   // deg = 1.0 (self-loop), cnt = 0
        g_cursor[i] = 0;
    }
    if (i < 128) g_flag[i] = 0;
    if (i < 6 * 4096)      g_wh[i] = __float2half(Wm[i]);
    else if (i < 7 * 4096) g_wh[i] = __float2half(Wl[i - 6 * 4096]);
}

__global__ void k_edge_deg(const int* __restrict__ ei,
                           const float* __restrict__ ew, int E, int N) {
    int i = blockIdx.x * blockDim.x + threadIdx.x;
    if (i >= E) return;
    int d = ei[E + i];
    if ((unsigned)d >= (unsigned)N) return;
    // fixed-point weight (2^-24 quantum) + count in one 64-bit atomic
    unsigned wfp = (unsigned)__float2uint_rn(ew[i] * 16777216.0f);
    atomicAdd(&g_degcnt[d], (1ULL << 40) | (unsigned long long)wfp);
}

// single-kernel: dinv + exclusive scan of counts (decoupled lookback).
__global__ void k_scan(int N, int E, int NB) {
    int b = blockIdx.x;
    int t = threadIdx.x;
    int g0 = b * 1024 + 4 * t;

    int vc[4];
#pragma unroll
    for (int k = 0; k < 4; k++) {
        int g = g0 + k;
        if (g < N) {
            unsigned long long p = g_degcnt[g];
            float dg = (float)(p & 0xFFFFFFFFFFULL) * 5.9604644775390625e-8f; // 2^-24
            float r = (dg > 0.0f) ? rsqrtf(dg) : 0.0f;
            g_dinv[g] = r;
            vc[k] = (int)(p >> 40);
        } else {
            vc[k] = 0;
        }
    }

    int v0 = vc[0], v1 = vc[1], v2 = vc[2], v3 = vc[3];
    int s = v0 + v1 + v2 + v3;
    int lane = t & 31, wid = t >> 5;
    int incl = s;
#pragma unroll
    for (int o = 1; o < 32; o <<= 1) {
        int x = __shfl_up_sync(0xffffffffu, incl, o);
        if (lane >= o) incl += x;
    }
    __shared__ int wsum[8];
    __shared__ int woff[8];
    __shared__ int sbase;
    if (lane == 31) wsum[wid] = incl;
    __syncthreads();
    if (t == 0) {
        int run = 0;
        for (int i = 0; i < 8; i++) { int x = wsum[i]; woff[i] = run; run += x; }
        int total = run;
        volatile int* vf = (volatile int*)g_flag;
        if (b == 0) {
            g_blkincl[0] = total;
            __threadfence();
            vf[0] = 2;
            sbase = 0;
        } else {
            g_blkagg[b] = total;
            __threadfence();
            vf[b] = 1;
            int acc = 0, p = b - 1;
            while (true) {
                int f;
                do { f = vf[p]; } while (f == 0);
                __threadfence();
                if (f == 2) { acc += g_blkincl[p]; break; }
                acc += g_blkagg[p];
                p--;
            }
            g_blkincl[b] = acc + total;
            __threadfence();
            vf[b] = 2;
            sbase = acc;
        }
        if (b == NB - 1) g_rowoff[N] = E;
    }
    __syncthreads();

    int excl = sbase + woff[wid] + (incl - s);
    if (g0 + 0 < N) g_rowoff[g0 + 0] = excl;
    if (g0 + 1 < N) g_rowoff[g0 + 1] = excl + v0;
    if (g0 + 2 < N) g_rowoff[g0 + 2] = excl + v0 + v1;
    if (g0 + 3 < N) g_rowoff[g0 + 3] = excl + v0 + v1 + v2;
}

__global__ void k_fill(const int* __restrict__ ei,
                       const float* __restrict__ ew, int E, int N) {
    int i = blockIdx.x * blockDim.x + threadIdx.x;
    if (i >= E) return;
    int s = ei[i];
    int d = ei[E + i];
    if ((unsigned)s >= (unsigned)N || (unsigned)d >= (unsigned)N) return;
    float nm = g_dinv[s] * ew[i];          // dinv[d] folded into agg epilogue
    int pos = g_rowoff[d] + atomicAdd(&g_cursor[d], 1);
    if ((unsigned)pos < (unsigned)MAXE) {
        unsigned long long pr =
            ((unsigned long long)__float_as_uint(nm) << 32) | (unsigned)s;
        g_epair[pos] = pr;
    }
}

// ------------------------- layer-0 transform (SIMT) -------------------------
// C[N,64] = x[N,15] @ W0[15,64], fp32 compute, fp16 store. Independent of the
// preprocessing chain -> launched on a forked stream.

__global__ void k_transform0(const float* __restrict__ A,
                             const float* __restrict__ W,
                             __half* __restrict__ C, int N) {
    __shared__ float As[15][68];
    __shared__ float Bs[15][68];
    int t = threadIdx.x;                 // 256 threads
    int n0 = blockIdx.x * 64;

    for (int idx = t; idx < 15 * 64; idx += 256) {
        int k = idx >> 6, f = idx & 63;
        Bs[k][f] = W[idx];
    }
    for (int idx = t; idx < 64 * 15; idx += 256) {
        int node = idx / 15;
        int k = idx % 15;
        int gn = n0 + node;
        As[k][node] = (gn < N) ? A[(size_t)gn * 15 + k] : 0.f;
    }
    __syncthreads();

    int tx = t & 15, ty = t >> 4;
    float acc[4][4];
#pragma unroll
    for (int i = 0; i < 4; i++)
#pragma unroll
        for (int j = 0; j < 4; j++) acc[i][j] = 0.f;

#pragma unroll
    for (int k = 0; k < 15; k++) {
        float4 a = *(const float4*)&As[k][4 * ty];
        float4 b = *(const float4*)&Bs[k][4 * tx];
        float av[4] = {a.x, a.y, a.z, a.w};
        float bv[4] = {b.x, b.y, b.z, b.w};
#pragma unroll
        for (int i = 0; i < 4; i++)
#pragma unroll
            for (int j = 0; j < 4; j++) acc[i][j] += av[i] * bv[j];
    }

#pragma unroll
    for (int i = 0; i < 4; i++) {
        int gn = n0 + 4 * ty + i;
        if (gn < N) {
            __half2 p0 = __floats2half2_rn(acc[i][0], acc[i][1]);
            __half2 p1 = __floats2half2_rn(acc[i][2], acc[i][3]);
            uint2 pk;
            pk.x = *(unsigned*)&p0;
            pk.y = *(unsigned*)&p1;
            *(uint2*)(C + (size_t)gn * 64 + 4 * tx) = pk;
        }
    }
}

// ---------------------- mid/final transform (tensor core) -------------------
// C[N,64] = A[N,64] @ W[64,64]; A,W fp16, fp32 accum via mma.m16n8k16.

__device__ __forceinline__ void mma16816(float c[4], unsigned a0, unsigned a1,
                                         unsigned a2, unsigned a3,
                                         unsigned b0, unsigned b1) {
    asm volatile(
        "mma.sync.aligned.m16n8k16.row.col.f32.f16.f16.f32 "
        "{%0,%1,%2,%3}, {%4,%5,%6,%7}, {%8,%9}, {%0,%1,%2,%3};\n"
        : "+f"(c[0]), "+f"(c[1]), "+f"(c[2]), "+f"(c[3])
        : "r"(a0), "r"(a1), "r"(a2), "r"(a3), "r"(b0), "r"(b1));
}

__global__ void __launch_bounds__(256) k_transform_tc(
    const __half* __restrict__ A,      // [N,64] fp16
    const __half* __restrict__ Wh,     // [64,64] fp16, k-major
    __half* __restrict__ C, int N)
{
    __shared__ __align__(16) __half As[128 * 72];   // row stride 72 halves
    __shared__ __align__(16) __half Wt[64 * 72];    // transposed [n][k]

    int tid = threadIdx.x;
    int n0 = blockIdx.x * 128;

    for (int i = tid; i < 4096; i += 256) {
        int k = i >> 6, n = i & 63;
        Wt[n * 72 + k] = Wh[i];
    }
    {
        const uint4* Ag = (const uint4*)A;   // 8 uint4 per 64-half row
#pragma unroll
        for (int r4 = 0; r4 < 4; r4++) {
            int q = tid + 256 * r4;          // 0..1023
            int r = q >> 3, u = q & 7;
            int gr = n0 + r;
            uint4 v = (gr < N) ? Ag[(size_t)gr * 8 + u]
                               : make_uint4(0u, 0u, 0u, 0u);
            *(uint4*)&As[r * 72 + u * 8] = v;
        }
    }
    __syncthreads();

    int lane = tid & 31, warp = tid >> 5;
    int g = lane >> 2, t = lane & 3;
    int m0 = warp * 16;

    float acc[8][4];
#pragma unroll
    for (int i = 0; i < 8; i++)
#pragma unroll
        for (int j = 0; j < 4; j++) acc[i][j] = 0.f;

    const unsigned* As2 = (const unsigned*)As;   // stride 36 uints
    const unsigned* Wt2 = (const unsigned*)Wt;

#pragma unroll
    for (int ks = 0; ks < 4; ks++) {
        int k8 = ks * 8;                         // k offset in uints
        unsigned a0 = As2[(m0 + g) * 36 + k8 + t];
        unsigned a1 = As2[(m0 + g + 8) * 36 + k8 + t];
        unsigned a2 = As2[(m0 + g) * 36 + k8 + 4 + t];
        unsigned a3 = As2[(m0 + g + 8) * 36 + k8 + 4 + t];
#pragma unroll
        for (int nt = 0; nt < 8; nt++) {
            unsigned b0 = Wt2[(nt * 8 + g) * 36 + k8 + t];
            unsigned b1 = Wt2[(nt * 8 + g) * 36 + k8 + 4 + t];
            mma16816(acc[nt], a0, a1, a2, a3, b0, b1);
        }
    }

    __half2* Cv = (__half2*)C;                   // 32 half2 per row
    int r0 = n0 + m0 + g;
    int r1 = r0 + 8;
#pragma unroll
    for (int nt = 0; nt < 8; nt++) {
        if (r0 < N) Cv[(size_t)r0 * 32 + nt * 4 + t] =
            __floats2half2_rn(acc[nt][0], acc[nt][1]);
        if (r1 < N) Cv[(size_t)r1 * 32 + nt * 4 + t] =
            __floats2half2_rn(acc[nt][2], acc[nt][3]);
    }
}

// ------------------------------- aggregation -------------------------------
// FROZEN round-9 loop: one warp per node; lane holds 2 features as one half2;
// fp32 accumulation; interleaved pairs, 1 uniform int4 per 2 edges.
// Epilogue: out = dinv[w] * acc + bias (dinv[d] factored out of edge norms).

template <bool FP16OUT>
__global__ void k_agg(const __half2* __restrict__ tin,
                      const float* __restrict__ bias,
                      void* __restrict__ outp, int N, int act) {
    int w = (blockIdx.x * blockDim.x + threadIdx.x) >> 5;
    int lane = threadIdx.x & 31;
    if (w >= N) return;

    float2 self = __half22float2(tin[(size_t)w * 32 + lane]);
    float sn = g_dinv[w];
    float ax = sn * self.x;          // acc gets sn*t_self; epilogue adds 2nd sn
    float ay = sn * self.y;
    float bx = 0.f, by = 0.f;

    int beg = g_rowoff[w];
    int end = g_rowoff[w + 1];
    int j = beg;

    // peel one edge if start is odd (int4 needs 16B = 2-pair alignment)
    if ((j & 1) && j < end) {
        unsigned long long p = g_epair[j];
        int s = (int)(unsigned)p;
        float m = __uint_as_float((unsigned)(p >> 32));
        float2 v = __half22float2(tin[(size_t)s * 32 + lane]);
        ax += m * v.x; ay += m * v.y;
        j++;
    }
    // 2 edges per uniform int4
    for (; j + 2 <= end; j += 2) {
        int4 pr = *(const int4*)&g_epair[j];
        int s0 = pr.x;
        float m0 = __int_as_float(pr.y);
        int s1 = pr.z;
        float m1 = __int_as_float(pr.w);
        float2 v0 = __half22float2(tin[(size_t)s0 * 32 + lane]);
        float2 v1 = __half22float2(tin[(size_t)s1 * 32 + lane]);
        ax += m0 * v0.x; ay += m0 * v0.y;
        bx += m1 * v1.x; by += m1 * v1.y;
    }
    // tail edge
    if (j < end) {
        unsigned long long p = g_epair[j];
        int s = (int)(unsigned)p;
        float m = __uint_as_float((unsigned)(p >> 32));
        float2 v = __half22float2(tin[(size_t)s * 32 + lane]);
        ax += m * v.x; ay += m * v.y;
    }
    ax += bx; ay += by;

    float2 b = ((const float2*)bias)[lane];
    ax = sn * ax + b.x;              // dinv[d] applied once to whole sum
    ay = sn * ay + b.y;
    if (act == 1) {
        ax = fmaxf(ax, 0.f);
        ay = fmaxf(ay, 0.f);
    } else {
        ax = 1.0f / (1.0f + __expf(-ax));
        ay = 1.0f / (1.0f + __expf(-ay));
    }
    if (FP16OUT) {
        ((__half2*)outp)[(size_t)w * 32 + lane] = __floats2half2_rn(ax, ay);
    } else {
        ((float2*)outp)[(size_t)w * 32 + lane] = make_float2(ax, ay);
    }
}

// --------------------------------- launcher --------------------------------

extern "C" void kernel_launch(void* const* d_in, const int* in_sizes, int n_in,
                              void* d_out, int out_size) {
    const float* x  = (const float*)d_in[0];
    const int*   ei = (const int*)d_in[1];     // int32 (JAX default, x64 off)
    const float* ew = (const float*)d_in[2];
    const float* W0 = (const float*)d_in[3];
    const float* b0 = (const float*)d_in[4];
    const float* Wm = (const float*)d_in[5];
    const float* bm = (const float*)d_in[6];
    const float* Wl = (const float*)d_in[7];
    const float* bl = (const float*)d_in[8];

    int N = in_sizes[0] / 15;
    int E = in_sizes[2];

    __half* t;
    __half* h;
    __half* wh;
    cudaGetSymbolAddress((void**)&t, g_t);
    cudaGetSymbolAddress((void**)&h, g_hh);
    cudaGetSymbolAddress((void**)&wh, g_wh);

    // side stream + fork/join events (host objects; created once, outside
    // capture on the first/correctness call; identical GPU work every call)
    static cudaStream_t s2 = nullptr;
    static cudaEvent_t evF = nullptr, evJ = nullptr;
    if (!s2) {
        cudaStreamCreateWithFlags(&s2, cudaStreamNonBlocking);
        cudaEventCreateWithFlags(&evF, cudaEventDisableTiming);
        cudaEventCreateWithFlags(&evJ, cudaEventDisableTiming);
    }

    int NB = (N + 1023) / 1024;

    // fork: transform0 (independent of CSR build) runs on s2
    cudaEventRecord(evF, 0);
    cudaStreamWaitEvent(s2, evF, 0);
    k_transform0<<<(N + 63) / 64, 256, 0, s2>>>(x, W0, t, N);
    cudaEventRecord(evJ, s2);

    // preprocessing chain on the main stream
    k_init<<<(N + 255) / 256, 256>>>(Wm, Wl, N);
    k_edge_deg<<<(E + 255) / 256, 256>>>(ei, ew, E, N);
    k_scan<<<NB, 256>>>(N, E, NB);
    k_fill<<<(E + 255) / 256, 256>>>(ei, ew, E, N);

    // join before layer-0 aggregation (needs t from s2)
    cudaStreamWaitEvent(0, evJ, 0);

    int gT = (N + 127) / 128;
    int gA = (N + 7) / 8;

    // layer 0: h = relu(dinv*(agg) + b0)
    k_agg<true><<<gA, 256>>>((const __half2*)t, b0, h, N, 1);

    // middle layers 1..6 (tensor-core transform)
    for (int i = 0; i < 6; i++) {
        k_transform_tc<<<gT, 256>>>(h, wh + (size_t)i * 4096, t, N);
        k_agg<true><<<gA, 256>>>((const __half2*)t, bm + (size_t)i * 64, h, N, 1);
    }

    // final layer + sigmoid -> d_out (fp32)
    k_transform_tc<<<gT, 256>>>(h, wh + (size_t)6 * 4096, t, N);
    k_agg<false><<<gA, 256>>>((const __half2*)t, bl, d_out, N, 2);
}

// round 16
// speedup vs baseline: 1.3803x; 1.0064x over previous
#include <cuda_runtime.h>
#include <cuda_fp16.h>
#include <cstdint>

// ---------------------------------------------------------------------------
// GCNEncoder: 8-layer GCN, N=100000, E=1.6M, F=15->64(x7)->64
// R15 platform + fork-point fix: transform0 overlaps ONLY k_fill (atomics,
// no inter-block spin), not the lookback k_scan (which it slowed 6->20us).
// h fp16; mid/final transforms = HMMA (fp32 accum); agg loop FROZEN (R9);
// k_fill stores m'=w*dinv[src]; agg applies dinv[dst] in epilogue.
// edge_index is int32 on device (JAX default, x64 disabled).
// ---------------------------------------------------------------------------

#define MAXN 131072
#define MAXE 1700000

__device__ __half g_t[MAXN * 64];        // transformed features (fp16)
__device__ __half g_hh[MAXN * 64];       // activations (fp16)
__device__ __half g_wh[7 * 4096];        // fp16 weights: Wm[0..5], Wl
__device__ unsigned long long g_degcnt[MAXN];  // (cnt<<40)|deg_fp24
__device__ float  g_dinv[MAXN];
__device__ int    g_cursor[MAXN];
__device__ int    g_rowoff[MAXN + 1];
__device__ int    g_blkagg[128];
__device__ int    g_blkincl[128];
__device__ int    g_flag[128];
__device__ __align__(16) unsigned long long g_epair[MAXE];  // (m'<<32)|src

// ------------------------------ preprocessing ------------------------------

__global__ void k_init(const float* __restrict__ Wm,
                       const float* __restrict__ Wl, int N) {
    int i = blockIdx.x * blockDim.x + threadIdx.x;
    if (i < N) {
        g_degcnt[i] = 16777216ULL;   // deg = 1.0 (self-loop), cnt = 0
        g_cursor[i] = 0;
    }
    if (i < 128) g_flag[i] = 0;
    if (i < 6 * 4096)      g_wh[i] = __float2half(Wm[i]);
    else if (i < 7 * 4096) g_wh[i] = __float2half(Wl[i - 6 * 4096]);
}

__global__ void k_edge_deg(const int* __restrict__ ei,
                           const float* __restrict__ ew, int E, int N) {
    int i = blockIdx.x * blockDim.x + threadIdx.x;
    if (i >= E) return;
    int d = ei[E + i];
    if ((unsigned)d >= (unsigned)N) return;
    // fixed-point weight (2^-24 quantum) + count in one 64-bit atomic
    unsigned wfp = (unsigned)__float2uint_rn(ew[i] * 16777216.0f);
    atomicAdd(&g_degcnt[d], (1ULL << 40) | (unsigned long long)wfp);
}

// single-kernel: dinv + exclusive scan of counts (decoupled lookback).
__global__ void k_scan(int N, int E, int NB) {
    int b = blockIdx.x;
    int t = threadIdx.x;
    int g0 = b * 1024 + 4 * t;

    int vc[4];
#pragma unroll
    for (int k = 0; k < 4; k++) {
        int g = g0 + k;
        if (g < N) {
            unsigned long long p = g_degcnt[g];
            float dg = (float)(p & 0xFFFFFFFFFFULL) * 5.9604644775390625e-8f; // 2^-24
            float r = (dg > 0.0f) ? rsqrtf(dg) : 0.0f;
            g_dinv[g] = r;
            vc[k] = (int)(p >> 40);
        } else {
            vc[k] = 0;
        }
    }

    int v0 = vc[0], v1 = vc[1], v2 = vc[2], v3 = vc[3];
    int s = v0 + v1 + v2 + v3;
    int lane = t & 31, wid = t >> 5;
    int incl = s;
#pragma unroll
    for (int o = 1; o < 32; o <<= 1) {
        int x = __shfl_up_sync(0xffffffffu, incl, o);
        if (lane >= o) incl += x;
    }
    __shared__ int wsum[8];
    __shared__ int woff[8];
    __shared__ int sbase;
    if (lane == 31) wsum[wid] = incl;
    __syncthreads();
    if (t == 0) {
        int run = 0;
        for (int i = 0; i < 8; i++) { int x = wsum[i]; woff[i] = run; run += x; }
        int total = run;
        volatile int* vf = (volatile int*)g_flag;
        if (b == 0) {
            g_blkincl[0] = total;
            __threadfence();
            vf[0] = 2;
            sbase = 0;
        } else {
            g_blkagg[b] = total;
            __threadfence();
            vf[b] = 1;
            int acc = 0, p = b - 1;
            while (true) {
                int f;
                do { f = vf[p]; } while (f == 0);
                __threadfence();
                if (f == 2) { acc += g_blkincl[p]; break; }
                acc += g_blkagg[p];
                p--;
            }
            g_blkincl[b] = acc + total;
            __threadfence();
            vf[b] = 2;
            sbase = acc;
        }
        if (b == NB - 1) g_rowoff[N] = E;
    }
    __syncthreads();

    int excl = sbase + woff[wid] + (incl - s);
    if (g0 + 0 < N) g_rowoff[g0 + 0] = excl;
    if (g0 + 1 < N) g_rowoff[g0 + 1] = excl + v0;
    if (g0 + 2 < N) g_rowoff[g0 + 2] = excl + v0 + v1;
    if (g0 + 3 < N) g_rowoff[g0 + 3] = excl + v0 + v1 + v2;
}

__global__ void k_fill(const int* __restrict__ ei,
                       const float* __restrict__ ew, int E, int N) {
    int i = blockIdx.x * blockDim.x + threadIdx.x;
    if (i >= E) return;
    int s = ei[i];
    int d = ei[E + i];
    if ((unsigned)s >= (unsigned)N || (unsigned)d >= (unsigned)N) return;
    float nm = g_dinv[s] * ew[i];          // dinv[d] folded into agg epilogue
    int pos = g_rowoff[d] + atomicAdd(&g_cursor[d], 1);
    if ((unsigned)pos < (unsigned)MAXE) {
        unsigned long long pr =
            ((unsigned long long)__float_as_uint(nm) << 32) | (unsigned)s;
        g_epair[pos] = pr;
    }
}

// ------------------------- layer-0 transform (SIMT) -------------------------
// C[N,64] = x[N,15] @ W0[15,64], fp32 compute, fp16 store. Independent of the
// CSR build -> forked to overlap with k_fill only.

__global__ void k_transform0(const float* __restrict__ A,
                             const float* __restrict__ W,
                             __half* __restrict__ C, int N) {
    __shared__ float As[15][68];
    __shared__ float Bs[15][68];
    int t = threadIdx.x;                 // 256 threads
    int n0 = blockIdx.x * 64;

    for (int idx = t; idx < 15 * 64; idx += 256) {
        int k = idx >> 6, f = idx & 63;
        Bs[k][f] = W[idx];
    }
    for (int idx = t; idx < 64 * 15; idx += 256) {
        int node = idx / 15;
        int k = idx % 15;
        int gn = n0 + node;
        As[k][node] = (gn < N) ? A[(size_t)gn * 15 + k] : 0.f;
    }
    __syncthreads();

    int tx = t & 15, ty = t >> 4;
    float acc[4][4];
#pragma unroll
    for (int i = 0; i < 4; i++)
#pragma unroll
        for (int j = 0; j < 4; j++) acc[i][j] = 0.f;

#pragma unroll
    for (int k = 0; k < 15; k++) {
        float4 a = *(const float4*)&As[k][4 * ty];
        float4 b = *(const float4*)&Bs[k][4 * tx];
        float av[4] = {a.x, a.y, a.z, a.w};
        float bv[4] = {b.x, b.y, b.z, b.w};
#pragma unroll
        for (int i = 0; i < 4; i++)
#pragma unroll
            for (int j = 0; j < 4; j++) acc[i][j] += av[i] * bv[j];
    }

#pragma unroll
    for (int i = 0; i < 4; i++) {
        int gn = n0 + 4 * ty + i;
        if (gn < N) {
            __half2 p0 = __floats2half2_rn(acc[i][0], acc[i][1]);
            __half2 p1 = __floats2half2_rn(acc[i][2], acc[i][3]);
            uint2 pk;
            pk.x = *(unsigned*)&p0;
            pk.y = *(unsigned*)&p1;
            *(uint2*)(C + (size_t)gn * 64 + 4 * tx) = pk;
        }
    }
}

// ---------------------- mid/final transform (tensor core) -------------------
// C[N,64] = A[N,64] @ W[64,64]; A,W fp16, fp32 accum via mma.m16n8k16.

__device__ __forceinline__ void mma16816(float c[4], unsigned a0, unsigned a1,
                                         unsigned a2, unsigned a3,
                                         unsigned b0, unsigned b1) {
    asm volatile(
        "mma.sync.aligned.m16n8k16.row.col.f32.f16.f16.f32 "
        "{%0,%1,%2,%3}, {%4,%5,%6,%7}, {%8,%9}, {%0,%1,%2,%3};\n"
        : "+f"(c[0]), "+f"(c[1]), "+f"(c[2]), "+f"(c[3])
        : "r"(a0), "r"(a1), "r"(a2), "r"(a3), "r"(b0), "r"(b1));
}

__global__ void __launch_bounds__(256) k_transform_tc(
    const __half* __restrict__ A,      // [N,64] fp16
    const __half* __restrict__ Wh,     // [64,64] fp16, k-major
    __half* __restrict__ C, int N)
{
    __shared__ __align__(16) __half As[128 * 72];   // row stride 72 halves
    __shared__ __align__(16) __half Wt[64 * 72];    // transposed [n][k]

    int tid = threadIdx.x;
    int n0 = blockIdx.x * 128;

    for (int i = tid; i < 4096; i += 256) {
        int k = i >> 6, n = i & 63;
        Wt[n * 72 + k] = Wh[i];
    }
    {
        const uint4* Ag = (const uint4*)A;   // 8 uint4 per 64-half row
#pragma unroll
        for (int r4 = 0; r4 < 4; r4++) {
            int q = tid + 256 * r4;          // 0..1023
            int r = q >> 3, u = q & 7;
            int gr = n0 + r;
            uint4 v = (gr < N) ? Ag[(size_t)gr * 8 + u]
                               : make_uint4(0u, 0u, 0u, 0u);
            *(uint4*)&As[r * 72 + u * 8] = v;
        }
    }
    __syncthreads();

    int lane = tid & 31, warp = tid >> 5;
    int g = lane >> 2, t = lane & 3;
    int m0 = warp * 16;

    float acc[8][4];
#pragma unroll
    for (int i = 0; i < 8; i++)
#pragma unroll
        for (int j = 0; j < 4; j++) acc[i][j] = 0.f;

    const unsigned* As2 = (const unsigned*)As;   // stride 36 uints
    const unsigned* Wt2 = (const unsigned*)Wt;

#pragma unroll
    for (int ks = 0; ks < 4; ks++) {
        int k8 = ks * 8;                         // k offset in uints
        unsigned a0 = As2[(m0 + g) * 36 + k8 + t];
        unsigned a1 = As2[(m0 + g + 8) * 36 + k8 + t];
        unsigned a2 = As2[(m0 + g) * 36 + k8 + 4 + t];
        unsigned a3 = As2[(m0 + g + 8) * 36 + k8 + 4 + t];
#pragma unroll
        for (int nt = 0; nt < 8; nt++) {
            unsigned b0 = Wt2[(nt * 8 + g) * 36 + k8 + t];
            unsigned b1 = Wt2[(nt * 8 + g) * 36 + k8 + 4 + t];
            mma16816(acc[nt], a0, a1, a2, a3, b0, b1);
        }
    }

    __half2* Cv = (__half2*)C;                   // 32 half2 per row
    int r0 = n0 + m0 + g;
    int r1 = r0 + 8;
#pragma unroll
    for (int nt = 0; nt < 8; nt++) {
        if (r0 < N) Cv[(size_t)r0 * 32 + nt * 4 + t] =
            __floats2half2_rn(acc[nt][0], acc[nt][1]);
        if (r1 < N) Cv[(size_t)r1 * 32 + nt * 4 + t] =
            __floats2half2_rn(acc[nt][2], acc[nt][3]);
    }
}

// ------------------------------- aggregation -------------------------------
// FROZEN round-9 loop: one warp per node; lane holds 2 features as one half2;
// fp32 accumulation; interleaved pairs, 1 uniform int4 per 2 edges.
// Epilogue: out = dinv[w] * acc + bias (dinv[d] factored out of edge norms).

template <bool FP16OUT>
__global__ void k_agg(const __half2* __restrict__ tin,
                      const float* __restrict__ bias,
                      void* __restrict__ outp, int N, int act) {
    int w = (blockIdx.x * blockDim.x + threadIdx.x) >> 5;
    int lane = threadIdx.x & 31;
    if (w >= N) return;

    float2 self = __half22float2(tin[(size_t)w * 32 + lane]);
    float sn = g_dinv[w];
    float ax = sn * self.x;          // acc gets sn*t_self; epilogue adds 2nd sn
    float ay = sn * self.y;
    float bx = 0.f, by = 0.f;

    int beg = g_rowoff[w];
    int end = g_rowoff[w + 1];
    int j = beg;

    // peel one edge if start is odd (int4 needs 16B = 2-pair alignment)
    if ((j & 1) && j < end) {
        unsigned long long p = g_epair[j];
        int s = (int)(unsigned)p;
        float m = __uint_as_float((unsigned)(p >> 32));
        float2 v = __half22float2(tin[(size_t)s * 32 + lane]);
        ax += m * v.x; ay += m * v.y;
        j++;
    }
    // 2 edges per uniform int4
    for (; j + 2 <= end; j += 2) {
        int4 pr = *(const int4*)&g_epair[j];
        int s0 = pr.x;
        float m0 = __int_as_float(pr.y);
        int s1 = pr.z;
        float m1 = __int_as_float(pr.w);
        float2 v0 = __half22float2(tin[(size_t)s0 * 32 + lane]);
        float2 v1 = __half22float2(tin[(size_t)s1 * 32 + lane]);
        ax += m0 * v0.x; ay += m0 * v0.y;
        bx += m1 * v1.x; by += m1 * v1.y;
    }
    // tail edge
    if (j < end) {
        unsigned long long p = g_epair[j];
        int s = (int)(unsigned)p;
        float m = __uint_as_float((unsigned)(p >> 32));
        float2 v = __half22float2(tin[(size_t)s * 32 + lane]);
        ax += m * v.x; ay += m * v.y;
    }
    ax += bx; ay += by;

    float2 b = ((const float2*)bias)[lane];
    ax = sn * ax + b.x;              // dinv[d] applied once to whole sum
    ay = sn * ay + b.y;
    if (act == 1) {
        ax = fmaxf(ax, 0.f);
        ay = fmaxf(ay, 0.f);
    } else {
        ax = 1.0f / (1.0f + __expf(-ax));
        ay = 1.0f / (1.0f + __expf(-ay));
    }
    if (FP16OUT) {
        ((__half2*)outp)[(size_t)w * 32 + lane] = __floats2half2_rn(ax, ay);
    } else {
        ((float2*)outp)[(size_t)w * 32 + lane] = make_float2(ax, ay);
    }
}

// --------------------------------- launcher --------------------------------

extern "C" void kernel_launch(void* const* d_in, const int* in_sizes, int n_in,
                              void* d_out, int out_size) {
    const float* x  = (const float*)d_in[0];
    const int*   ei = (const int*)d_in[1];     // int32 (JAX default, x64 off)
    const float* ew = (const float*)d_in[2];
    const float* W0 = (const float*)d_in[3];
    const float* b0 = (const float*)d_in[4];
    const float* Wm = (const float*)d_in[5];
    const float* bm = (const float*)d_in[6];
    const float* Wl = (const float*)d_in[7];
    const float* bl = (const float*)d_in[8];

    int N = in_sizes[0] / 15;
    int E = in_sizes[2];

    __half* t;
    __half* h;
    __half* wh;
    cudaGetSymbolAddress((void**)&t, g_t);
    cudaGetSymbolAddress((void**)&h, g_hh);
    cudaGetSymbolAddress((void**)&wh, g_wh);

    // side stream + fork/join events (host objects; created once, outside
    // capture on the first/correctness call; identical GPU work every call)
    static cudaStream_t s2 = nullptr;
    static cudaEvent_t evF = nullptr, evJ = nullptr;
    if (!s2) {
        cudaStreamCreateWithFlags(&s2, cudaStreamNonBlocking);
        cudaEventCreateWithFlags(&evF, cudaEventDisableTiming);
        cudaEventCreateWithFlags(&evJ, cudaEventDisableTiming);
    }

    int NB = (N + 1023) / 1024;

    // preprocessing chain on the main stream (scan runs WITHOUT co-residents)
    k_init<<<(N + 255) / 256, 256>>>(Wm, Wl, N);
    k_edge_deg<<<(E + 255) / 256, 256>>>(ei, ew, E, N);
    k_scan<<<NB, 256>>>(N, E, NB);

    // fork AFTER scan: transform0 overlaps only k_fill
    cudaEventRecord(evF, 0);
    cudaStreamWaitEvent(s2, evF, 0);
    k_transform0<<<(N + 63) / 64, 256, 0, s2>>>(x, W0, t, N);
    cudaEventRecord(evJ, s2);

    k_fill<<<(E + 255) / 256, 256>>>(ei, ew, E, N);

    // join before layer-0 aggregation (needs t from s2)
    cudaStreamWaitEvent(0, evJ, 0);

    int gT = (N + 127) / 128;
    int gA = (N + 7) / 8;

    // layer 0: h = relu(dinv*(agg) + b0)
    k_agg<true><<<gA, 256>>>((const __half2*)t, b0, h, N, 1);

    // middle layers 1..6 (tensor-core transform)
    for (int i = 0; i < 6; i++) {
        k_transform_tc<<<gT, 256>>>(h, wh + (size_t)i * 4096, t, N);
        k_agg<true><<<gA, 256>>>((const __half2*)t, bm + (size_t)i * 64, h, N, 1);
    }

    // final layer + sigmoid -> d_out (fp32)
    k_transform_tc<<<gT, 256>>>(h, wh + (size_t)6 * 4096, t, N);
    k_agg<false><<<gA, 256>>>((const __half2*)t, bl, d_out, N, 2);
}